// round 1
// baseline (speedup 1.0000x reference)
#include <cuda_runtime.h>
#include <cuda_bf16.h>
#include <math.h>

// Problem shape (fixed by setup_inputs)
#define Bb 2
#define Hh 16
#define Ss 2048
#define Dd 64
#define BH (Bb*Hh)

#define ROWS 16          // query rows per block
#define TK   128         // K-tile (t) per SMEM stage
#define NKT  (Ss/TK)     // 16
#define PAD  65          // smem row stride (floats) -> conflict-free scalar LDS
#define SCALE 0.125f     // 1/sqrt(64)

// smem: sS[ROWS][Ss] | sQ[ROWS][PAD] | sK[TK][PAD]
#define SMEM_FLOATS (ROWS*Ss + ROWS*PAD + TK*PAD)

__global__ void __launch_bounds__(256, 1)
sdpa_fused_kernel(const float* __restrict__ q,
                  const float* __restrict__ k,
                  const float* __restrict__ v,
                  const int*   __restrict__ masks,
                  float* __restrict__ out)
{
    extern __shared__ float smem[];
    float* sS = smem;                  // ROWS * Ss
    float* sQ = sS + ROWS * Ss;        // ROWS * PAD
    float* sK = sQ + ROWS * PAD;       // TK * PAD

    const int tid  = threadIdx.x;
    const int lane = tid & 31;
    const int rg   = tid >> 5;         // warp id 0..7
    const int r0   = rg * 2;           // this warp's 2 query rows in QK phase

    const int bh = blockIdx.y;         // 0..31
    const int b  = bh >> 4;            // H = 16
    const int s0 = blockIdx.x * ROWS;

    const float* qg = q + ((size_t)bh * Ss + s0) * Dd;
    const float* kg = k + (size_t)bh * Ss * Dd;
    const float* vg = v + (size_t)bh * Ss * Dd;
    const int*   mg = masks + ((size_t)b * Ss + s0) * Ss;
    float* outg = out + ((size_t)bh * Ss + s0) * Dd;
    float* attg = out + (size_t)Bb * Hh * Ss * Dd + ((size_t)bh * Ss + s0) * Ss;

    // ---- load Q tile: 16x64 floats = 256 float4, one per thread ----
    {
        int r  = tid >> 4;
        int d4 = (tid & 15) << 2;
        float4 qq = *(const float4*)(qg + (size_t)r * Dd + d4);
        float* dst = &sQ[r * PAD + d4];
        dst[0] = qq.x; dst[1] = qq.y; dst[2] = qq.z; dst[3] = qq.w;
    }

    // ---- QK^T: scores tile into sS, masked + scaled ----
    for (int kt = 0; kt < NKT; ++kt) {
        __syncthreads();   // protect sK reuse (and Q load on first iter)
        // load K tile: TK x 64 floats = 2048 float4, 8 per thread
        #pragma unroll
        for (int i = 0; i < 8; ++i) {
            int fid = tid + i * 256;
            int t   = fid >> 4;
            int d4  = (fid & 15) << 2;
            float4 kk = *(const float4*)(kg + (size_t)(kt * TK + t) * Dd + d4);
            float* dst = &sK[t * PAD + d4];
            dst[0] = kk.x; dst[1] = kk.y; dst[2] = kk.z; dst[3] = kk.w;
        }
        __syncthreads();

        float acc[2][4];
        #pragma unroll
        for (int i = 0; i < 2; ++i)
            #pragma unroll
            for (int j = 0; j < 4; ++j) acc[i][j] = 0.f;

        #pragma unroll 16
        for (int d = 0; d < Dd; ++d) {
            float q0 = sQ[r0 * PAD + d];
            float q1 = sQ[(r0 + 1) * PAD + d];
            #pragma unroll
            for (int j = 0; j < 4; ++j) {
                float kk = sK[(lane + j * 32) * PAD + d];
                acc[0][j] += q0 * kk;
                acc[1][j] += q1 * kk;
            }
        }
        // mask fill (-1e-12 where mask==0) and store to sS
        #pragma unroll
        for (int j = 0; j < 4; ++j) {
            int tloc = lane + j * 32;
            int t    = kt * TK + tloc;
            int m0 = mg[(size_t)r0 * Ss + t];
            int m1 = mg[(size_t)(r0 + 1) * Ss + t];
            sS[r0 * Ss + t]       = m0 ? acc[0][j] * SCALE : -1e-12f;
            sS[(r0 + 1) * Ss + t] = m1 ? acc[1][j] * SCALE : -1e-12f;
        }
    }
    __syncthreads();

    // ---- softmax per row (2 rows per warp), write attention matrix ----
    #pragma unroll
    for (int rr = 0; rr < 2; ++rr) {
        int r = r0 + rr;
        const float* row = &sS[r * Ss];
        float m = -3.402823466e38f;
        for (int i = lane; i < Ss; i += 32) m = fmaxf(m, row[i]);
        #pragma unroll
        for (int o = 16; o; o >>= 1) m = fmaxf(m, __shfl_xor_sync(0xFFFFFFFFu, m, o));
        float sum = 0.f;
        for (int i = lane; i < Ss; i += 32) sum += __expf(row[i] - m);
        #pragma unroll
        for (int o = 16; o; o >>= 1) sum += __shfl_xor_sync(0xFFFFFFFFu, sum, o);
        float inv = 1.f / sum;
        float* arow = attg + (size_t)r * Ss;
        for (int i = lane; i < Ss; i += 32) arow[i] = __expf(row[i] - m) * inv;
    }

    // ---- PV: output = masked_scores @ V (faithful bug: raw scores, not softmax) ----
    // warp rg owns t in [rg*256, rg*256+256); lane owns cols {2*lane, 2*lane+1}
    float po[16][2];
    #pragma unroll
    for (int r = 0; r < 16; ++r) { po[r][0] = 0.f; po[r][1] = 0.f; }

    const int tbase = rg * 256;
    const int c0 = 2 * lane;
    for (int tt = 0; tt < 256; tt += 4) {
        int t = tbase + tt;
        float2 v0 = *(const float2*)(vg + (size_t)(t + 0) * Dd + c0);
        float2 v1 = *(const float2*)(vg + (size_t)(t + 1) * Dd + c0);
        float2 v2 = *(const float2*)(vg + (size_t)(t + 2) * Dd + c0);
        float2 v3 = *(const float2*)(vg + (size_t)(t + 3) * Dd + c0);
        #pragma unroll
        for (int r = 0; r < 16; ++r) {
            float4 s4 = *(const float4*)&sS[r * Ss + t];
            po[r][0] += s4.x * v0.x; po[r][1] += s4.x * v0.y;
            po[r][0] += s4.y * v1.x; po[r][1] += s4.y * v1.y;
            po[r][0] += s4.z * v2.x; po[r][1] += s4.z * v2.y;
            po[r][0] += s4.w * v3.x; po[r][1] += s4.w * v3.y;
        }
    }

    // cross-warp reduction of partial outputs via smem (reuse sS region)
    __syncthreads();           // everyone done reading sS
    float* red = sS;           // [8][16][64]
    #pragma unroll
    for (int r = 0; r < 16; ++r) {
        red[(rg * 16 + r) * 64 + c0]     = po[r][0];
        red[(rg * 16 + r) * 64 + c0 + 1] = po[r][1];
    }
    __syncthreads();
    for (int i = tid; i < 16 * 64; i += 256) {
        int r = i >> 6, c = i & 63;
        float s = 0.f;
        #pragma unroll
        for (int w = 0; w < 8; ++w) s += red[(w * 16 + r) * 64 + c];
        outg[(size_t)r * Dd + c] = s;
    }
}

extern "C" void kernel_launch(void* const* d_in, const int* in_sizes, int n_in,
                              void* d_out, int out_size)
{
    const float* q = (const float*)d_in[0];
    const float* k = (const float*)d_in[1];
    const float* v = (const float*)d_in[2];
    const int* masks = (const int*)d_in[3];
    float* out = (float*)d_out;

    size_t smem_bytes = (size_t)SMEM_FLOATS * sizeof(float);  // ~168.5 KB
    cudaFuncSetAttribute(sdpa_fused_kernel,
                         cudaFuncAttributeMaxDynamicSharedMemorySize,
                         (int)smem_bytes);

    dim3 grid(Ss / ROWS, BH);   // (128, 32)
    dim3 block(256);
    sdpa_fused_kernel<<<grid, block, smem_bytes>>>(q, k, v, masks, out);
}

// round 2
// speedup vs baseline: 1.2331x; 1.2331x over previous
#include <cuda_runtime.h>
#include <cuda_bf16.h>
#include <math.h>

// Shape fixed by setup_inputs
#define Bb 2
#define Hh 16
#define Ss 2048
#define Dd 64
#define BH (Bb*Hh)

#define ROWS 16            // query rows per block
#define TK   256           // K-tile per stage
#define NKT  (Ss/TK)       // 8
#define KPAD 68            // sQ/sK row stride (floats): 16B-aligned, conflict-free
#define SSTR 2052          // sS row stride (floats): 16B-aligned, de-conflicts stores
#define SCALE 0.125f

// smem: sS[16][2052] | sQ[16][68] | sK[256][68]
#define SMEM_FLOATS (ROWS*SSTR + ROWS*KPAD + TK*KPAD)

// packed mask bits: B * S * S / 32 words = 1 MB
__device__ unsigned int g_maskbits[(size_t)Bb * Ss * Ss / 32];

__device__ __forceinline__ unsigned long long ffma2(unsigned long long a,
                                                    unsigned long long b,
                                                    unsigned long long c)
{
    unsigned long long d;
    asm("fma.rn.f32x2 %0, %1, %2, %3;" : "=l"(d) : "l"(a), "l"(b), "l"(c));
    return d;
}

__device__ __forceinline__ unsigned long long pack2(float lo, float hi)
{
    unsigned long long r;
    asm("mov.b64 %0, {%1, %2};" : "=l"(r) : "f"(lo), "f"(hi));
    return r;
}

__device__ __forceinline__ float sum2(unsigned long long v)
{
    float lo, hi;
    asm("mov.b64 {%0, %1}, %2;" : "=f"(lo), "=f"(hi) : "l"(v));
    return lo + hi;
}

__global__ void pack_mask_kernel(const int* __restrict__ masks)
{
    int e = blockIdx.x * 256 + threadIdx.x;      // B*S*S elements
    int val = masks[e] != 0;
    unsigned bal = __ballot_sync(0xFFFFFFFFu, val);
    if ((threadIdx.x & 31) == 0) g_maskbits[e >> 5] = bal;
}

__global__ void __launch_bounds__(256, 1)
sdpa_fused_kernel(const float* __restrict__ q,
                  const float* __restrict__ k,
                  const float* __restrict__ v,
                  float* __restrict__ out)
{
    extern __shared__ float smem[];
    float* sS = smem;                       // [16][SSTR]
    float* sQ = sS + ROWS * SSTR;           // [16][KPAD]
    float* sK = sQ + ROWS * KPAD;           // [TK][KPAD]

    const int tid  = threadIdx.x;
    const int lane = tid & 31;
    const int w    = tid >> 5;              // warp 0..7

    const int bh = blockIdx.y;
    const int b  = bh >> 4;                 // H = 16
    const int s0 = blockIdx.x * ROWS;

    const float* qg = q + ((size_t)bh * Ss + s0) * Dd;
    const float* kg = k + (size_t)bh * Ss * Dd;
    const float* vg = v + (size_t)bh * Ss * Dd;
    float* outg = out + ((size_t)bh * Ss + s0) * Dd;
    float* attg = out + (size_t)BH * Ss * Dd + ((size_t)bh * Ss + s0) * Ss;

    // ---- load Q tile: 16x64, one float4 per thread ----
    {
        int r  = tid >> 4;
        int d4 = (tid & 15) << 2;
        float4 qq = *(const float4*)(qg + (size_t)r * Dd + d4);
        float* dst = &sQ[r * KPAD + d4];
        dst[0] = qq.x; dst[1] = qq.y; dst[2] = qq.z; dst[3] = qq.w;
    }

    // ---- QK^T with f32x2 packed FMAs (pack over d-pairs) ----
    // warp w covers t in [w*32, w*32+32) of each 256-t stage
    // thread tile: rows (lane&3)+4i (i<4), t  w*32+(lane>>2)+8j (j<4)
    const int rbase = lane & 3;
    const int tsub  = lane >> 2;

    for (int kt = 0; kt < NKT; ++kt) {
        __syncthreads();
        // load K tile: 256x64 = 4096 float4, 16 per thread
        #pragma unroll
        for (int i = 0; i < 16; ++i) {
            int fid = tid + i * 256;
            int t   = fid >> 4;
            int d4  = (fid & 15) << 2;
            float4 kk = *(const float4*)(kg + (size_t)(kt * TK + t) * Dd + d4);
            float* dst = &sK[t * KPAD + d4];
            dst[0] = kk.x; dst[1] = kk.y; dst[2] = kk.z; dst[3] = kk.w;
        }
        __syncthreads();

        // mask words: one 32-bit word covers this warp's 32-t window for a row
        unsigned mw[4];
        #pragma unroll
        for (int i = 0; i < 4; ++i) {
            int r = rbase + 4 * i;
            mw[i] = g_maskbits[(size_t)b * (Ss * Ss / 32) + (size_t)(s0 + r) * (Ss / 32)
                               + kt * (TK / 32) + w];
        }

        unsigned long long acc[4][4];
        #pragma unroll
        for (int i = 0; i < 4; ++i)
            #pragma unroll
            for (int j = 0; j < 4; ++j) acc[i][j] = 0ull;

        #pragma unroll 4
        for (int d = 0; d < Dd; d += 4) {
            ulonglong2 qv[4], kv[4];
            #pragma unroll
            for (int i = 0; i < 4; ++i)
                qv[i] = *(const ulonglong2*)&sQ[(rbase + 4 * i) * KPAD + d];
            #pragma unroll
            for (int j = 0; j < 4; ++j)
                kv[j] = *(const ulonglong2*)&sK[(w * 32 + tsub + 8 * j) * KPAD + d];
            #pragma unroll
            for (int i = 0; i < 4; ++i)
                #pragma unroll
                for (int j = 0; j < 4; ++j) {
                    acc[i][j] = ffma2(qv[i].x, kv[j].x, acc[i][j]);
                    acc[i][j] = ffma2(qv[i].y, kv[j].y, acc[i][j]);
                }
        }

        #pragma unroll
        for (int i = 0; i < 4; ++i) {
            int r = rbase + 4 * i;
            #pragma unroll
            for (int j = 0; j < 4; ++j) {
                int tl  = w * 32 + tsub + 8 * j;
                int bit = (mw[i] >> (tsub + 8 * j)) & 1;
                float val = bit ? sum2(acc[i][j]) * SCALE : -1e-12f;
                sS[r * SSTR + kt * TK + tl] = val;
            }
        }
    }
    __syncthreads();

    // ---- softmax per row (2 rows per warp) -> attention matrix ----
    #pragma unroll
    for (int rr = 0; rr < 2; ++rr) {
        int r = 2 * w + rr;
        const float* row = &sS[r * SSTR];
        float m = -3.402823466e38f;
        for (int i = lane * 4; i < Ss; i += 128) {
            float4 x = *(const float4*)&row[i];
            m = fmaxf(m, fmaxf(fmaxf(x.x, x.y), fmaxf(x.z, x.w)));
        }
        #pragma unroll
        for (int o = 16; o; o >>= 1) m = fmaxf(m, __shfl_xor_sync(0xFFFFFFFFu, m, o));
        float sum = 0.f;
        for (int i = lane * 4; i < Ss; i += 128) {
            float4 x = *(const float4*)&row[i];
            sum += __expf(x.x - m) + __expf(x.y - m) + __expf(x.z - m) + __expf(x.w - m);
        }
        #pragma unroll
        for (int o = 16; o; o >>= 1) sum += __shfl_xor_sync(0xFFFFFFFFu, sum, o);
        float inv = 1.f / sum;
        float* arow = attg + (size_t)r * Ss;
        for (int i = lane * 4; i < Ss; i += 128) {
            float4 x = *(const float4*)&row[i];
            float4 y;
            y.x = __expf(x.x - m) * inv;
            y.y = __expf(x.y - m) * inv;
            y.z = __expf(x.z - m) * inv;
            y.w = __expf(x.w - m) * inv;
            *(float4*)&arow[i] = y;
        }
    }

    // ---- PV: out = masked_scores @ V, f32x2 packed over t-pairs ----
    // warp-pair p = w>>1 owns t in [p*512, p*512+512); half h = w&1 owns cols h*32+lane
    const int p = w >> 1;
    const int c = (w & 1) * 32 + lane;
    const int tbase = p * 512;

    unsigned long long acc[16];
    #pragma unroll
    for (int r = 0; r < 16; ++r) acc[r] = 0ull;

    const float* vcol = vg + c;
    // prefetch first group
    float v0 = vcol[(size_t)(tbase + 0) * Dd];
    float v1 = vcol[(size_t)(tbase + 1) * Dd];
    float v2 = vcol[(size_t)(tbase + 2) * Dd];
    float v3 = vcol[(size_t)(tbase + 3) * Dd];

    for (int t = 0; t < 512; t += 4) {
        float n0, n1, n2, n3;
        if (t + 4 < 512) {
            n0 = vcol[(size_t)(tbase + t + 4) * Dd];
            n1 = vcol[(size_t)(tbase + t + 5) * Dd];
            n2 = vcol[(size_t)(tbase + t + 6) * Dd];
            n3 = vcol[(size_t)(tbase + t + 7) * Dd];
        } else { n0 = n1 = n2 = n3 = 0.f; }

        unsigned long long p01 = pack2(v0, v1);
        unsigned long long p23 = pack2(v2, v3);
        #pragma unroll
        for (int r = 0; r < 16; ++r) {
            ulonglong2 s2 = *(const ulonglong2*)&sS[r * SSTR + tbase + t];
            acc[r] = ffma2(s2.x, p01, acc[r]);
            acc[r] = ffma2(s2.y, p23, acc[r]);
        }
        v0 = n0; v1 = n1; v2 = n2; v3 = n3;
    }

    // cross-warp-pair reduction via smem (reuse sK region, untouched since QK)
    float* red = sK;                        // [4][16][64] = 16 KB
    #pragma unroll
    for (int r = 0; r < 16; ++r)
        red[(p * 16 + r) * 64 + c] = sum2(acc[r]);
    __syncthreads();

    #pragma unroll
    for (int i = 0; i < 4; ++i) {
        int idx = tid + i * 256;            // 1024 outputs
        int r = idx >> 6, cc = idx & 63;
        float s = 0.f;
        #pragma unroll
        for (int pp = 0; pp < 4; ++pp) s += red[(pp * 16 + r) * 64 + cc];
        outg[(size_t)r * Dd + cc] = s;
    }
}

extern "C" void kernel_launch(void* const* d_in, const int* in_sizes, int n_in,
                              void* d_out, int out_size)
{
    const float* q = (const float*)d_in[0];
    const float* k = (const float*)d_in[1];
    const float* v = (const float*)d_in[2];
    const int* masks = (const int*)d_in[3];
    float* out = (float*)d_out;

    // pack mask into bits (B*S*S = 8,388,608 elements)
    pack_mask_kernel<<<(Bb * Ss * Ss) / 256, 256>>>(masks);

    size_t smem_bytes = (size_t)SMEM_FLOATS * sizeof(float);   // ~200.5 KB
    cudaFuncSetAttribute(sdpa_fused_kernel,
                         cudaFuncAttributeMaxDynamicSharedMemorySize,
                         (int)smem_bytes);

    dim3 grid(Ss / ROWS, BH);   // (128, 32)
    dim3 block(256);
    sdpa_fused_kernel<<<grid, block, smem_bytes>>>(q, k, v, out);
}

// round 4
// speedup vs baseline: 1.5575x; 1.2630x over previous
#include <cuda_runtime.h>
#include <cstdint>

#define Bb 2
#define Hh 16
#define Ss 2048
#define Dd 64
#define BH (Bb*Hh)
#define SCALE 0.125f
#define CHUNK 64
#define NCH (Ss/CHUNK)     // 32

// ---------------- packed mask bits: 1 MB ----------------
__device__ unsigned int g_maskbits[(size_t)Bb * Ss * Ss / 32];

__global__ void pack_mask_kernel(const int* __restrict__ masks)
{
    int e = blockIdx.x * 256 + threadIdx.x;
    int val = masks[e] != 0;
    unsigned bal = __ballot_sync(0xFFFFFFFFu, val);
    if ((threadIdx.x & 31) == 0) g_maskbits[e >> 5] = bal;
}

// ---------------- helpers ----------------
__device__ __forceinline__ uint32_t cvt_tf32(float x) {
    uint32_t b;
    asm("cvt.rna.tf32.f32 %0, %1;" : "=r"(b) : "f"(x));
    return b;
}
__device__ __forceinline__ float tf32hi(float x) { return __uint_as_float(cvt_tf32(x)); }

// mma.sync m16n8k8 tf32: D += A*B  (A 16x8 row, B 8x8 col)
__device__ __forceinline__ void mma8(float4& d, float a0, float a1, float a2, float a3,
                                     float b0, float b1)
{
    asm volatile(
        "mma.sync.aligned.m16n8k8.row.col.f32.tf32.tf32.f32 "
        "{%0,%1,%2,%3}, {%4,%5,%6,%7}, {%8,%9}, {%0,%1,%2,%3};"
        : "+f"(d.x), "+f"(d.y), "+f"(d.z), "+f"(d.w)
        : "r"(__float_as_uint(a0)), "r"(__float_as_uint(a1)),
          "r"(__float_as_uint(a2)), "r"(__float_as_uint(a3)),
          "r"(__float_as_uint(b0)), "r"(__float_as_uint(b1)));
}

// smem layout (float offsets)
#define Q2H 0
#define Q2L 8192
#define K2H 16384
#define K2L 20480
#define VTH 24576
#define VTL 28672
#define S2H 32768
#define S2L 40960
#define STG 49152     // 64 x 68
#define INV 53504     // 128
#define SMEM_FLOATS 53632

__global__ void __launch_bounds__(256, 1)
sdpa_mma_kernel(const float* __restrict__ q,
                const float* __restrict__ k,
                const float* __restrict__ v,
                float* __restrict__ out)
{
    extern __shared__ float sm[];
    float2* q2h = (float2*)(sm + Q2H);
    float2* q2l = (float2*)(sm + Q2L);
    float2* k2h = (float2*)(sm + K2H);
    float2* k2l = (float2*)(sm + K2L);
    float2* vth = (float2*)(sm + VTH);
    float2* vtl = (float2*)(sm + VTL);
    float2* s2h = (float2*)(sm + S2H);
    float2* s2l = (float2*)(sm + S2L);
    float*  stg = sm + STG;
    float*  sInv = sm + INV;

    const int tid  = threadIdx.x;
    const int lane = tid & 31;
    const int w    = tid >> 5;
    const int g    = lane >> 2;      // groupID 0..7
    const int tig  = lane & 3;       // threadID_in_group

    const int bh = blockIdx.y;
    const int b  = bh >> 4;
    const int s0 = blockIdx.x * 128;

    const float* qg = q + ((size_t)bh * Ss + s0) * Dd;
    const float* kg = k + (size_t)bh * Ss * Dd;
    const float* vg = v + (size_t)bh * Ss * Dd;
    float* outg = out + ((size_t)bh * Ss + s0) * Dd;
    float* attg = out + (size_t)BH * Ss * Dd + ((size_t)bh * Ss + s0) * Ss;

    // ---- load Q (128x64) -> paired/swizzled hi/lo smem ----
    #pragma unroll
    for (int it = 0; it < 4; ++it) {
        int id = tid + it * 256;             // 1024 items
        int r  = id >> 3, ks = id & 7;
        const float4* p = (const float4*)(qg + (size_t)r * Dd + ks * 8);
        float4 x = p[0], y = p[1];
        float4 hx, hy, lx, ly;
        hx.x = tf32hi(x.x); lx.x = tf32hi(x.x - hx.x);
        hx.y = tf32hi(x.y); lx.y = tf32hi(x.y - hx.y);
        hx.z = tf32hi(x.z); lx.z = tf32hi(x.z - hx.z);
        hx.w = tf32hi(x.w); lx.w = tf32hi(x.w - hx.w);
        hy.x = tf32hi(y.x); ly.x = tf32hi(y.x - hy.x);
        hy.y = tf32hi(y.y); ly.y = tf32hi(y.y - hy.y);
        hy.z = tf32hi(y.z); ly.z = tf32hi(y.z - hy.z);
        hy.w = tf32hi(y.w); ly.w = tf32hi(y.w - hy.w);
        int ib = ((ks ^ (r & 3)) << 2);
        float4* dh = (float4*)(q2h + (size_t)r * 32 + ib);
        dh[0] = make_float4(hx.x, hy.x, hx.y, hy.y);
        dh[1] = make_float4(hx.z, hy.z, hx.w, hy.w);
        float4* dl = (float4*)(q2l + (size_t)r * 32 + ib);
        dl[0] = make_float4(lx.x, ly.x, lx.y, ly.y);
        dl[1] = make_float4(lx.z, ly.z, lx.w, ly.w);
    }

    const int r0 = w * 16 + g;          // CTA-local rows r0, r0+8
    const int sw = (g & 3) << 2;        // swizzle for rows r0/r0+8 and cols 8j+g

    const unsigned long long* m64 = (const unsigned long long*)g_maskbits;
    const size_t mrow0 = ((size_t)b * Ss + s0 + r0) * (Ss / 64);
    const size_t mrow1 = mrow0 + 8 * (Ss / 64);

    float rs0 = 0.f, rs1 = 0.f;
    float4 po[8];
    #pragma unroll
    for (int j = 0; j < 8; ++j) po[j] = make_float4(0.f, 0.f, 0.f, 0.f);

    float* att0 = attg + (size_t)r0 * Ss;
    float* att1 = attg + (size_t)(r0 + 8) * Ss;

    for (int kt = 0; kt < NCH; ++kt) {
        const int t0 = kt * CHUNK;

        // prefetch K/V chunk (2 items x 32B each)
        float4 kx[2][2], vx[2][2];
        int tt_[2], ks_[2];
        #pragma unroll
        for (int it = 0; it < 2; ++it) {
            int id = tid + it * 256;
            tt_[it] = id >> 3; ks_[it] = id & 7;
            const float4* kp = (const float4*)(kg + (size_t)(t0 + tt_[it]) * Dd + ks_[it] * 8);
            kx[it][0] = kp[0]; kx[it][1] = kp[1];
            const float4* vp = (const float4*)(vg + (size_t)(t0 + tt_[it]) * Dd + ks_[it] * 8);
            vx[it][0] = vp[0]; vx[it][1] = vp[1];
        }

        unsigned long long mw0 = m64[mrow0 + kt];
        unsigned long long mw1 = m64[mrow1 + kt];

        __syncthreads();   // prev QK (K2) + prev transpose (stage) reads done

        // write K2 hi/lo, stage V
        #pragma unroll
        for (int it = 0; it < 2; ++it) {
            int tt = tt_[it], ks = ks_[it];
            float4 x = kx[it][0], y = kx[it][1];
            float4 hx, hy, lx, ly;
            hx.x = tf32hi(x.x); lx.x = tf32hi(x.x - hx.x);
            hx.y = tf32hi(x.y); lx.y = tf32hi(x.y - hx.y);
            hx.z = tf32hi(x.z); lx.z = tf32hi(x.z - hx.z);
            hx.w = tf32hi(x.w); lx.w = tf32hi(x.w - hx.w);
            hy.x = tf32hi(y.x); ly.x = tf32hi(y.x - hy.x);
            hy.y = tf32hi(y.y); ly.y = tf32hi(y.y - hy.y);
            hy.z = tf32hi(y.z); ly.z = tf32hi(y.z - hy.z);
            hy.w = tf32hi(y.w); ly.w = tf32hi(y.w - hy.w);
            int ib = ((ks ^ (tt & 3)) << 2);
            float4* dh = (float4*)(k2h + (size_t)tt * 32 + ib);
            dh[0] = make_float4(hx.x, hy.x, hx.y, hy.y);
            dh[1] = make_float4(hx.z, hy.z, hx.w, hy.w);
            float4* dl = (float4*)(k2l + (size_t)tt * 32 + ib);
            dl[0] = make_float4(lx.x, ly.x, lx.y, ly.y);
            dl[1] = make_float4(lx.z, ly.z, lx.w, ly.w);
            float* sp = stg + tt * 68 + ks * 8;
            *(float4*)(sp)     = vx[it][0];
            *(float4*)(sp + 4) = vx[it][1];
        }
        __syncthreads();

        // transpose stage -> VT2 hi/lo  (pairs over t: {t, t+4})
        #pragma unroll
        for (int it = 0; it < 2; ++it) {
            int id = tid + it * 256;
            int d = id & 63, ks = id >> 6;
            float v0 = stg[(8 * ks + 0) * 68 + d];
            float v1 = stg[(8 * ks + 1) * 68 + d];
            float v2 = stg[(8 * ks + 2) * 68 + d];
            float v3 = stg[(8 * ks + 3) * 68 + d];
            float v4 = stg[(8 * ks + 4) * 68 + d];
            float v5 = stg[(8 * ks + 5) * 68 + d];
            float v6 = stg[(8 * ks + 6) * 68 + d];
            float v7 = stg[(8 * ks + 7) * 68 + d];
            float h0 = tf32hi(v0), l0 = tf32hi(v0 - h0);
            float h1 = tf32hi(v1), l1 = tf32hi(v1 - h1);
            float h2 = tf32hi(v2), l2 = tf32hi(v2 - h2);
            float h3 = tf32hi(v3), l3 = tf32hi(v3 - h3);
            float h4 = tf32hi(v4), l4 = tf32hi(v4 - h4);
            float h5 = tf32hi(v5), l5 = tf32hi(v5 - h5);
            float h6 = tf32hi(v6), l6 = tf32hi(v6 - h6);
            float h7 = tf32hi(v7), l7 = tf32hi(v7 - h7);
            int ib = ((ks ^ (d & 3)) << 2);
            float4* dh = (float4*)(vth + (size_t)d * 32 + ib);
            dh[0] = make_float4(h0, h4, h1, h5);
            dh[1] = make_float4(h2, h6, h3, h7);
            float4* dl = (float4*)(vtl + (size_t)d * 32 + ib);
            dl[0] = make_float4(l0, l4, l1, l5);
            dl[1] = make_float4(l2, l6, l3, l7);
        }

        // ---- QK mma: scores chunk (rows r0/r0+8 block x 64 t) ----
        float4 cf[8];
        #pragma unroll
        for (int j = 0; j < 8; ++j) cf[j] = make_float4(0.f, 0.f, 0.f, 0.f);

        #pragma unroll
        for (int ks = 0; ks < 8; ++ks) {
            int ia = (4 * ks + tig) ^ sw;
            float2 ah  = q2h[(size_t)r0 * 32 + ia];
            float2 ah8 = q2h[(size_t)(r0 + 8) * 32 + ia];
            float2 al  = q2l[(size_t)r0 * 32 + ia];
            float2 al8 = q2l[(size_t)(r0 + 8) * 32 + ia];
            #pragma unroll
            for (int j = 0; j < 8; ++j) {
                int tl = 8 * j + g;
                float2 bh = k2h[(size_t)tl * 32 + ia];
                float2 bl = k2l[(size_t)tl * 32 + ia];
                mma8(cf[j], ah.x, ah8.x, ah.y, ah8.y, bh.x, bh.y);
                mma8(cf[j], ah.x, ah8.x, ah.y, ah8.y, bl.x, bl.y);
                mma8(cf[j], al.x, al8.x, al.y, al8.y, bh.x, bh.y);
            }
        }

        // ---- epilogue: mask/scale, exp+rowsum, att store, S2 hi/lo ----
        #pragma unroll
        for (int j = 0; j < 8; ++j) {
            int c0 = 8 * j + 2 * tig;
            float s00 = ((mw0 >> c0) & 1ull)       ? cf[j].x * SCALE : -1e-12f;
            float s01 = ((mw0 >> (c0 + 1)) & 1ull) ? cf[j].y * SCALE : -1e-12f;
            float s10 = ((mw1 >> c0) & 1ull)       ? cf[j].z * SCALE : -1e-12f;
            float s11 = ((mw1 >> (c0 + 1)) & 1ull) ? cf[j].w * SCALE : -1e-12f;

            float e00 = __expf(s00), e01 = __expf(s01);
            float e10 = __expf(s10), e11 = __expf(s11);
            rs0 += e00 + e01; rs1 += e10 + e11;
            *(float2*)(att0 + t0 + c0) = make_float2(e00, e01);
            *(float2*)(att1 + t0 + c0) = make_float2(e10, e11);

            float h00 = tf32hi(s00), l00 = tf32hi(s00 - h00);
            float h01 = tf32hi(s01), l01 = tf32hi(s01 - h01);
            float h10 = tf32hi(s10), l10 = tf32hi(s10 - h10);
            float h11 = tf32hi(s11), l11 = tf32hi(s11 - h11);

            float ph00 = __shfl_xor_sync(0xFFFFFFFFu, h00, 2);
            float ph01 = __shfl_xor_sync(0xFFFFFFFFu, h01, 2);
            float ph10 = __shfl_xor_sync(0xFFFFFFFFu, h10, 2);
            float ph11 = __shfl_xor_sync(0xFFFFFFFFu, h11, 2);
            float pl00 = __shfl_xor_sync(0xFFFFFFFFu, l00, 2);
            float pl01 = __shfl_xor_sync(0xFFFFFFFFu, l01, 2);
            float pl10 = __shfl_xor_sync(0xFFFFFFFFu, l10, 2);
            float pl11 = __shfl_xor_sync(0xFFFFFFFFu, l11, 2);

            if (tig < 2) {
                int idx = (4 * j + 2 * tig) ^ sw;
                *(float4*)(s2h + (size_t)r0 * 32 + idx) = make_float4(h00, ph00, h01, ph01);
                *(float4*)(s2l + (size_t)r0 * 32 + idx) = make_float4(l00, pl00, l01, pl01);
            } else {
                int idx = (4 * j + 2 * (tig - 2)) ^ sw;
                *(float4*)(s2h + (size_t)(r0 + 8) * 32 + idx) = make_float4(ph10, h10, ph11, h11);
                *(float4*)(s2l + (size_t)(r0 + 8) * 32 + idx) = make_float4(pl10, l10, pl11, l11);
            }
        }
        __syncthreads();

        // ---- PV mma: out += S_chunk @ V_chunk ----
        #pragma unroll
        for (int ks = 0; ks < 8; ++ks) {
            int ia = (4 * ks + tig) ^ sw;
            float2 ah  = s2h[(size_t)r0 * 32 + ia];
            float2 ah8 = s2h[(size_t)(r0 + 8) * 32 + ia];
            float2 al  = s2l[(size_t)r0 * 32 + ia];
            float2 al8 = s2l[(size_t)(r0 + 8) * 32 + ia];
            #pragma unroll
            for (int j = 0; j < 8; ++j) {
                int dl = 8 * j + g;
                float2 bh = vth[(size_t)dl * 32 + ia];
                float2 bl = vtl[(size_t)dl * 32 + ia];
                mma8(po[j], ah.x, ah8.x, ah.y, ah8.y, bh.x, bh.y);
                mma8(po[j], ah.x, ah8.x, ah.y, ah8.y, bl.x, bl.y);
                mma8(po[j], al.x, al8.x, al.y, al8.y, bh.x, bh.y);
            }
        }
    }

    // ---- write output ----
    #pragma unroll
    for (int j = 0; j < 8; ++j) {
        int c0 = 8 * j + 2 * tig;
        *(float2*)(outg + (size_t)r0 * Dd + c0)       = make_float2(po[j].x, po[j].y);
        *(float2*)(outg + (size_t)(r0 + 8) * Dd + c0) = make_float2(po[j].z, po[j].w);
    }

    // ---- rowsum reduce + normalize att ----
    rs0 += __shfl_xor_sync(0xFFFFFFFFu, rs0, 1);
    rs0 += __shfl_xor_sync(0xFFFFFFFFu, rs0, 2);
    rs1 += __shfl_xor_sync(0xFFFFFFFFu, rs1, 1);
    rs1 += __shfl_xor_sync(0xFFFFFFFFu, rs1, 2);
    if (tig == 0) {
        sInv[r0]     = 1.f / rs0;
        sInv[r0 + 8] = 1.f / rs1;
    }
    __syncthreads();

    for (int r = 0; r < 128; ++r) {
        float iv = sInv[r];
        float* row = attg + (size_t)r * Ss + tid * 8;
        float4 a = *(const float4*)(row);
        float4 c = *(const float4*)(row + 4);
        a.x *= iv; a.y *= iv; a.z *= iv; a.w *= iv;
        c.x *= iv; c.y *= iv; c.z *= iv; c.w *= iv;
        *(float4*)(row)     = a;
        *(float4*)(row + 4) = c;
    }
}

extern "C" void kernel_launch(void* const* d_in, const int* in_sizes, int n_in,
                              void* d_out, int out_size)
{
    const float* q = (const float*)d_in[0];
    const float* k = (const float*)d_in[1];
    const float* v = (const float*)d_in[2];
    const int* masks = (const int*)d_in[3];
    float* out = (float*)d_out;

    pack_mask_kernel<<<(Bb * Ss * Ss) / 256, 256>>>(masks);

    size_t smem_bytes = (size_t)SMEM_FLOATS * sizeof(float);   // 214,528 B
    cudaFuncSetAttribute(sdpa_mma_kernel,
                         cudaFuncAttributeMaxDynamicSharedMemorySize,
                         (int)smem_bytes);

    dim3 grid(Ss / 128, BH);   // (16, 32)
    sdpa_mma_kernel<<<grid, 256, smem_bytes>>>(q, k, v, out);
}

// round 5
// speedup vs baseline: 3.3770x; 2.1682x over previous
#include <cuda_runtime.h>
#include <cstdint>

#define Bb 2
#define Hh 16
#define Ss 2048
#define Dd 64
#define BH (Bb*Hh)
#define SCALE 0.125f

// ---------------- global scratch ----------------
// packed mask bits: 1 MB
__device__ unsigned int g_maskbits[(size_t)Bb * Ss * Ss / 32];
// fragment-ready bf16 planes: [bh][chunk32][row64][granule16] of 8B = 8 MB each
#define TILE_ULL 1024
__device__ unsigned long long gKhi[(size_t)BH * 32 * TILE_ULL];
__device__ unsigned long long gKlo[(size_t)BH * 32 * TILE_ULL];
__device__ unsigned long long gVhi[(size_t)BH * 32 * TILE_ULL];
__device__ unsigned long long gVlo[(size_t)BH * 32 * TILE_ULL];

__global__ void pack_mask_kernel(const int* __restrict__ masks)
{
    int e = blockIdx.x * 256 + threadIdx.x;
    int val = masks[e] != 0;
    unsigned bal = __ballot_sync(0xFFFFFFFFu, val);
    if ((threadIdx.x & 31) == 0) g_maskbits[e >> 5] = bal;
}

// ---------------- helpers ----------------
__device__ __forceinline__ uint32_t smem_u32(const void* p) {
    uint32_t a;
    asm("{ .reg .u64 t; cvta.to.shared.u64 t, %1; cvt.u32.u64 %0, t; }" : "=r"(a) : "l"(p));
    return a;
}
__device__ __forceinline__ uint32_t packpair(float s0, float s1) {
    uint32_t p;  // low 16 = s0, high 16 = s1
    asm("cvt.rn.bf16x2.f32 %0, %1, %2;" : "=r"(p) : "f"(s1), "f"(s0));
    return p;
}
__device__ __forceinline__ uint32_t packhi(float s0, float s1, float& h0, float& h1) {
    uint32_t p = packpair(s0, s1);
    h0 = __uint_as_float(p << 16);
    h1 = __uint_as_float(p & 0xFFFF0000u);
    return p;
}
// granule offset (8B units): row-major 16 granules/row, XOR swizzle -> conflict-free LDS.64
__device__ __forceinline__ int goff(int row, int gidx) {
    return row * 16 + (gidx ^ ((row & 3) << 2));
}
// mma m16n8k16 bf16: D += A*B
__device__ __forceinline__ void mma16(float4& d, uint32_t a0, uint32_t a1, uint32_t a2,
                                      uint32_t a3, uint32_t b0, uint32_t b1)
{
    asm volatile(
        "mma.sync.aligned.m16n8k16.row.col.f32.bf16.bf16.f32 "
        "{%0,%1,%2,%3}, {%4,%5,%6,%7}, {%8,%9}, {%0,%1,%2,%3};"
        : "+f"(d.x), "+f"(d.y), "+f"(d.z), "+f"(d.w)
        : "r"(a0), "r"(a1), "r"(a2), "r"(a3), "r"(b0), "r"(b1));
}

// ---------------- prepass: K -> QK B-frag planes ----------------
__global__ void split_k_kernel(const float* __restrict__ k)
{
    int idx = blockIdx.x * 256 + threadIdx.x;    // BH*2048*16
    int gidx = idx & 15;
    int tglob = (idx >> 4) & 2047;
    int bh = idx >> 15;
    int ks = gidx >> 2, tig = gidx & 3;
    const float* kr = k + ((size_t)bh * Ss + tglob) * Dd + 16 * ks + 2 * tig;
    float2 p0 = *(const float2*)kr;
    float2 p1 = *(const float2*)(kr + 8);
    float h00, h01, h10, h11;
    uint32_t b0h = packhi(p0.x, p0.y, h00, h01);
    uint32_t b1h = packhi(p1.x, p1.y, h10, h11);
    uint32_t b0l = packpair(p0.x - h00, p0.y - h01);
    uint32_t b1l = packpair(p1.x - h10, p1.y - h11);
    int kt = tglob >> 6, tl = tglob & 63;
    size_t base = ((size_t)bh * 32 + kt) * TILE_ULL + goff(tl, gidx);
    gKhi[base] = (unsigned long long)b0h | ((unsigned long long)b1h << 32);
    gKlo[base] = (unsigned long long)b0l | ((unsigned long long)b1l << 32);
}

// ---------------- prepass: V -> PV B-frag planes (transposed pairing over t) ----------------
__global__ void split_vt_kernel(const float* __restrict__ v)
{
    int idx = blockIdx.x * 256 + threadIdx.x;    // BH*32*16*64
    int d  = idx & 63;
    int gidx = (idx >> 6) & 15;
    int kt = (idx >> 10) & 31;
    int bh = idx >> 15;
    int ks = gidx >> 2, tig = gidx & 3;
    int t0 = kt * 64 + 16 * ks + 2 * tig;
    const float* vb = v + (size_t)bh * Ss * Dd + d;
    float v0 = vb[(size_t)t0 * Dd];
    float v1 = vb[(size_t)(t0 + 1) * Dd];
    float v2 = vb[(size_t)(t0 + 8) * Dd];
    float v3 = vb[(size_t)(t0 + 9) * Dd];
    float h0, h1, h2, h3;
    uint32_t b0h = packhi(v0, v1, h0, h1);
    uint32_t b1h = packhi(v2, v3, h2, h3);
    uint32_t b0l = packpair(v0 - h0, v1 - h1);
    uint32_t b1l = packpair(v2 - h2, v3 - h3);
    size_t base = ((size_t)bh * 32 + kt) * TILE_ULL + goff(d, gidx);
    gVhi[base] = (unsigned long long)b0h | ((unsigned long long)b1h << 32);
    gVlo[base] = (unsigned long long)b0l | ((unsigned long long)b1l << 32);
}

// ---------------- smem layout (bytes) ----------------
#define SQH  0u
#define SQL  16384u
#define BUF  32768u        // 2 x 32768: [Khi 8K][Klo 8K][Vhi 8K][Vlo 8K]
#define SINV 98304u
#define SMEM_TOTAL (98304 + 512)

__global__ void __launch_bounds__(256, 2)
sdpa_main_kernel(const float* __restrict__ q, float* __restrict__ out)
{
    extern __shared__ char smc[];
    const uint32_t sb = smem_u32(smc);
    float* sInv = (float*)(smc + SINV);

    const int tid  = threadIdx.x;
    const int lane = tid & 31;
    const int w    = tid >> 5;
    const int g    = lane >> 2;
    const int tig  = lane & 3;

    const int bh = blockIdx.y;
    const int b  = bh >> 4;
    const int s0 = blockIdx.x * 128;

    const float* qg = q + ((size_t)bh * Ss + s0) * Dd;
    float* outg = out + ((size_t)bh * Ss + s0) * Dd;
    float* attg = out + (size_t)BH * Ss * Dd + ((size_t)bh * Ss + s0) * Ss;

    const size_t tilebase = (size_t)bh * 32;

    // ---- issue cp.async for chunk kt into buf[kt&1] ----
    auto issue = [&](int kt) {
        uint32_t dstb = sb + BUF + (uint32_t)(kt & 1) * 32768u;
        const unsigned long long* srcs[4] = {
            gKhi + (tilebase + kt) * TILE_ULL, gKlo + (tilebase + kt) * TILE_ULL,
            gVhi + (tilebase + kt) * TILE_ULL, gVlo + (tilebase + kt) * TILE_ULL };
        #pragma unroll
        for (int pl = 0; pl < 4; ++pl) {
            const char* src = (const char*)srcs[pl];
            uint32_t dst = dstb + pl * 8192u;
            #pragma unroll
            for (int i = 0; i < 2; ++i) {
                int off = (tid + i * 256) * 16;
                asm volatile("cp.async.cg.shared.global [%0], [%1], 16;"
                             :: "r"(dst + off), "l"(src + off));
            }
        }
    };

    issue(0);
    asm volatile("cp.async.commit_group;");

    // ---- build Q A-frag planes in smem ----
    #pragma unroll
    for (int i = 0; i < 8; ++i) {
        int idx = tid + i * 256;             // 2048 granules
        int r = idx >> 4, gi = idx & 15;
        int ks = gi >> 2, tg = gi & 3;
        const float* qr = qg + (size_t)r * Dd + 16 * ks + 2 * tg;
        float2 p0 = *(const float2*)qr;
        float2 p1 = *(const float2*)(qr + 8);
        float h00, h01, h10, h11;
        uint32_t b0h = packhi(p0.x, p0.y, h00, h01);
        uint32_t b1h = packhi(p1.x, p1.y, h10, h11);
        uint32_t b0l = packpair(p0.x - h00, p0.y - h01);
        uint32_t b1l = packpair(p1.x - h10, p1.y - h11);
        int go = goff(r, gi);
        *(uint2*)(smc + SQH + go * 8) = make_uint2(b0h, b1h);
        *(uint2*)(smc + SQL + go * 8) = make_uint2(b0l, b1l);
    }
    __syncthreads();

    // ---- hoist Q fragments to registers (constant across chunks) ----
    const int r0 = w * 16 + g;
    uint2 qh[4][2], ql[4][2];
    #pragma unroll
    for (int ks = 0; ks < 4; ++ks) {
        qh[ks][0] = *(const uint2*)(smc + SQH + goff(r0,     4 * ks + tig) * 8);
        qh[ks][1] = *(const uint2*)(smc + SQH + goff(r0 + 8, 4 * ks + tig) * 8);
        ql[ks][0] = *(const uint2*)(smc + SQL + goff(r0,     4 * ks + tig) * 8);
        ql[ks][1] = *(const uint2*)(smc + SQL + goff(r0 + 8, 4 * ks + tig) * 8);
    }

    const unsigned long long* m64 = (const unsigned long long*)g_maskbits;
    const size_t mrow0 = ((size_t)b * Ss + s0 + r0) * (Ss / 64);
    const size_t mrow1 = mrow0 + 8 * (Ss / 64);

    float rs0 = 0.f, rs1 = 0.f;
    float4 po[8];
    #pragma unroll
    for (int j = 0; j < 8; ++j) po[j] = make_float4(0.f, 0.f, 0.f, 0.f);

    float* att0 = attg + (size_t)r0 * Ss;
    float* att1 = attg + (size_t)(r0 + 8) * Ss;

    for (int kt = 0; kt < 32; ++kt) {
        if (kt < 31) {
            issue(kt + 1);
            asm volatile("cp.async.commit_group;");
            asm volatile("cp.async.wait_group 1;");
        } else {
            asm volatile("cp.async.wait_group 0;");
        }
        __syncthreads();    // tiles for chunk kt visible to all warps

        const char* kb  = smc + BUF + (kt & 1) * 32768;
        const char* kbl = kb + 8192;
        const char* vb  = kb + 16384;
        const char* vbl = kb + 24576;

        unsigned long long mw0 = m64[mrow0 + kt];
        unsigned long long mw1 = m64[mrow1 + kt];

        // ---- QK: 128x64 scores via bf16x3 ----
        float4 cf[8];
        #pragma unroll
        for (int j = 0; j < 8; ++j) cf[j] = make_float4(0.f, 0.f, 0.f, 0.f);

        #pragma unroll
        for (int ks = 0; ks < 4; ++ks) {
            uint2 aH0 = qh[ks][0], aH8 = qh[ks][1];
            uint2 aL0 = ql[ks][0], aL8 = ql[ks][1];
            #pragma unroll
            for (int j = 0; j < 8; ++j) {
                int ro = goff(8 * j + g, 4 * ks + tig) * 8;
                uint2 bH = *(const uint2*)(kb + ro);
                uint2 bL = *(const uint2*)(kbl + ro);
                mma16(cf[j], aH0.x, aH8.x, aH0.y, aH8.y, bH.x, bH.y);
                mma16(cf[j], aH0.x, aH8.x, aH0.y, aH8.y, bL.x, bL.y);
                mma16(cf[j], aL0.x, aL8.x, aL0.y, aL8.y, bH.x, bH.y);
            }
        }

        // ---- epilogue fused with PV (C-frag -> A-frag identity) ----
        const int t0k = kt * 64;
        #pragma unroll
        for (int ks2 = 0; ks2 < 4; ++ks2) {
            uint32_t pa[2][2], pb[2][2];   // [u=j-half][hi/lo], rows g / g+8
            #pragma unroll
            for (int u = 0; u < 2; ++u) {
                int j = 2 * ks2 + u;
                int c0 = 8 * j + 2 * tig;
                float4 c = cf[j];
                float s00 = ((mw0 >> c0) & 1ull)       ? c.x * SCALE : -1e-12f;
                float s01 = ((mw0 >> (c0 + 1)) & 1ull) ? c.y * SCALE : -1e-12f;
                float s10 = ((mw1 >> c0) & 1ull)       ? c.z * SCALE : -1e-12f;
                float s11 = ((mw1 >> (c0 + 1)) & 1ull) ? c.w * SCALE : -1e-12f;
                float e00 = __expf(s00), e01 = __expf(s01);
                float e10 = __expf(s10), e11 = __expf(s11);
                rs0 += e00 + e01; rs1 += e10 + e11;
                *(float2*)(att0 + t0k + c0) = make_float2(e00, e01);
                *(float2*)(att1 + t0k + c0) = make_float2(e10, e11);
                float h0, h1;
                pa[u][0] = packhi(s00, s01, h0, h1);
                pa[u][1] = packpair(s00 - h0, s01 - h1);
                pb[u][0] = packhi(s10, s11, h0, h1);
                pb[u][1] = packpair(s10 - h0, s11 - h1);
            }
            #pragma unroll
            for (int j = 0; j < 8; ++j) {
                int ro = goff(8 * j + g, 4 * ks2 + tig) * 8;
                uint2 bH = *(const uint2*)(vb + ro);
                uint2 bL = *(const uint2*)(vbl + ro);
                mma16(po[j], pa[0][0], pb[0][0], pa[1][0], pb[1][0], bH.x, bH.y);
                mma16(po[j], pa[0][0], pb[0][0], pa[1][0], pb[1][0], bL.x, bL.y);
                mma16(po[j], pa[0][1], pb[0][1], pa[1][1], pb[1][1], bH.x, bH.y);
            }
        }
        __syncthreads();    // all warps done reading buf[kt&1] before it is re-filled
    }

    // ---- write output ----
    #pragma unroll
    for (int j = 0; j < 8; ++j) {
        int c0 = 8 * j + 2 * tig;
        *(float2*)(outg + (size_t)r0 * Dd + c0)       = make_float2(po[j].x, po[j].y);
        *(float2*)(outg + (size_t)(r0 + 8) * Dd + c0) = make_float2(po[j].z, po[j].w);
    }

    // ---- rowsum reduce + normalize att ----
    rs0 += __shfl_xor_sync(0xFFFFFFFFu, rs0, 1);
    rs0 += __shfl_xor_sync(0xFFFFFFFFu, rs0, 2);
    rs1 += __shfl_xor_sync(0xFFFFFFFFu, rs1, 1);
    rs1 += __shfl_xor_sync(0xFFFFFFFFu, rs1, 2);
    if (tig == 0) {
        sInv[r0]     = 1.f / rs0;
        sInv[r0 + 8] = 1.f / rs1;
    }
    __syncthreads();

    for (int r = 0; r < 128; ++r) {
        float iv = sInv[r];
        float* row = attg + (size_t)r * Ss + tid * 8;
        float4 a = *(const float4*)(row);
        float4 c = *(const float4*)(row + 4);
        a.x *= iv; a.y *= iv; a.z *= iv; a.w *= iv;
        c.x *= iv; c.y *= iv; c.z *= iv; c.w *= iv;
        *(float4*)(row)     = a;
        *(float4*)(row + 4) = c;
    }
}

extern "C" void kernel_launch(void* const* d_in, const int* in_sizes, int n_in,
                              void* d_out, int out_size)
{
    const float* q = (const float*)d_in[0];
    const float* k = (const float*)d_in[1];
    const float* v = (const float*)d_in[2];
    const int* masks = (const int*)d_in[3];
    float* out = (float*)d_out;

    pack_mask_kernel<<<(Bb * Ss * Ss) / 256, 256>>>(masks);
    split_k_kernel<<<(BH * Ss * 16) / 256, 256>>>(k);
    split_vt_kernel<<<(BH * 32 * 16 * 64) / 256, 256>>>(v);

    cudaFuncSetAttribute(sdpa_main_kernel,
                         cudaFuncAttributeMaxDynamicSharedMemorySize, SMEM_TOTAL);

    dim3 grid(Ss / 128, BH);   // (16, 32)
    sdpa_main_kernel<<<grid, 256, SMEM_TOTAL>>>(q, out);
}